// round 8
// baseline (speedup 1.0000x reference)
#include <cuda_runtime.h>
#include <cuda_bf16.h>

// Soft-DTW forward, gamma=1, B=128, N=M=512.
// Exp-domain DP: E = exp(-R); E[i][j] = exp(-D[i-1][j-1]) * (E[i-1][j-1] + E[i-1][j] + E[i][j-1]).
// Anti-diagonal wavefront, one block per batch, one thread per column.
// Block-wide power-of-2 renormalization every 32 steps keeps E in fp32 range;
// integer exponent accumulator restores the log at the end.

#define NROW 512
#define NCOL 512
#define NTH  512
#define PRE  16                 // prefetch ring depth (registers)
#define LN2F 0.69314718055994530942f

__global__ __launch_bounds__(NTH, 1)
void softdtw_exp_kernel(const float* __restrict__ D, float* __restrict__ out) {
    __shared__ float sh[2][NTH + 1];   // halo buffers; sh[*][0] is the j=0 boundary (E=0)
    __shared__ float red[16];          // per-warp max for renormalization

    const int t = threadIdx.x;         // column j = t+1 (1-indexed)
    const int b = blockIdx.x;
    const float* Db = D + (size_t)b * NROW * NCOL + t;   // base of column t

    // init boundaries: E[0][j>=1] = 0, E[i][0] = 0, E[0][0] = 1
    sh[0][t] = 0.0f;
    sh[1][t] = 0.0f;
    if (t == 0) { sh[0][NTH] = 0.0f; sh[1][NTH] = 0.0f; }

    float p1    = 0.0f;                       // E[i-1][j]  (own previous row)
    float Ldiag = (t == 0) ? 1.0f : 0.0f;     // E[i-1][j-1] (neighbor, two steps back); E[0][0]=1
    int   esum  = 0;                          // accumulated power-of-2 exponent

    // Prefill prefetch ring: slot k holds D for step s=k+1 -> row r = clamp(k - t)
    float ring[PRE];
#pragma unroll
    for (int k = 0; k < PRE; ++k) {
        int r = k - t;
        r = max(r, 0); r = min(r, NROW - 1);
        ring[k] = Db[r * NCOL];
    }
    __syncthreads();

    // 1024 steps (last step is a harmless no-op for all threads: i = 1024-t >= 513)
    // 64 chunks of 16; renormalize every 2 chunks (32 steps).
    int s = 1;
    for (int c = 0; c < 64; ++c) {
#pragma unroll
        for (int k = 0; k < PRE; ++k, ++s) {
            const int rb = k & 1;              // (s-1)&1, compile-time per k
            const int wb = rb ^ 1;             // s&1

            float L1   = sh[rb][t];            // E[i][j-1] (neighbor, previous step)
            float dval = ring[k];

            // refill slot for step s+PRE: row = s+PRE - t - 1, clamped
            {
                int r = s + PRE - t - 1;
                r = max(r, 0); r = min(r, NROW - 1);
                ring[k] = Db[r * NCOL];
            }

            // i = s - t. Pre-active threads (i <= 0) compute zeros (correct boundary
            // propagation); frozen threads (i > 512) must not touch state.
            if (s - t <= NROW) {
                float w = __expf(-dval);                 // off the dependency chain
                float v = w * ((L1 + p1) + Ldiag);
                sh[wb][t + 1] = v;
                p1 = v;
            }
            Ldiag = L1;                                  // neighbor's row becomes next diag
            __syncthreads();
        }

        if (c & 1) {
            // Renormalize the frontier by an exact power of two.
            // Last completed step s-1 is a multiple of 16 -> its write buffer is 0.
            float m = p1;                                 // all E >= 0
#pragma unroll
            for (int o = 16; o; o >>= 1)
                m = fmaxf(m, __shfl_xor_sync(0xffffffffu, m, o));
            if ((t & 31) == 0) red[t >> 5] = m;
            __syncthreads();
            float M = red[0];
#pragma unroll
            for (int q = 1; q < 16; ++q) M = fmaxf(M, red[q]);

            int e = ((__float_as_int(M) >> 23) & 0xFF) - 127;  // ilogb(M), M>0 normal
            if (e > 100) e = 100;
            if (e < -100) e = -100;
            if (e != 0) {
                float sc = __int_as_float((127 - e) << 23);    // exact 2^-e
                p1    *= sc;
                Ldiag *= sc;
                sh[0][t + 1] = p1;       // buffer 0 = the one read next step
                esum  += e;
            }
            __syncthreads();
        }
    }

    // Thread 511 holds E[512][512] (computed at step 1023, frozen at 1024).
    if (t == NTH - 1)
        out[b] = -((float)esum + __log2f(p1)) * LN2F;
}

extern "C" void kernel_launch(void* const* d_in, const int* in_sizes, int n_in,
                              void* d_out, int out_size) {
    const float* D = (const float*)d_in[0];
    float* out = (float*)d_out;
    int B = in_sizes[0] / (NROW * NCOL);   // 128
    softdtw_exp_kernel<<<B, NTH>>>(D, out);
}

// round 9
// speedup vs baseline: 1.0303x; 1.0303x over previous
#include <cuda_runtime.h>
#include <cuda_bf16.h>

// Soft-DTW forward, gamma=1, B=128, N=M=512.
// Exp-domain DP: E = exp(-R); E[i][j] = exp(-D[i-1][j-1]) * (E[i-1][j-1] + E[i-1][j] + E[i][j-1]).
// Anti-diagonal wavefront, one block per batch, one thread per column.
// Block-wide power-of-2 renormalization every 32 steps keeps E in fp32 range;
// integer exponent accumulator restores the log at the end.

#define NROW 512
#define NCOL 512
#define NTH  512
#define PRE  16                 // prefetch ring depth (registers)
#define LN2F 0.69314718055994530942f

__global__ __launch_bounds__(NTH, 1)
void softdtw_exp_kernel(const float* __restrict__ D, float* __restrict__ out) {
    __shared__ float sh[2][NTH + 1];   // halo buffers; sh[*][0] is the j=0 boundary (E=0)
    __shared__ float red[16];          // per-warp max for renormalization

    const int t = threadIdx.x;         // column j = t+1 (1-indexed)
    const int b = blockIdx.x;
    const float* Db = D + (size_t)b * NROW * NCOL + t;   // base of column t

    // init boundaries: E[0][j>=1] = 0, E[i][0] = 0, E[0][0] = 1
    sh[0][t] = 0.0f;
    sh[1][t] = 0.0f;
    if (t == 0) { sh[0][NTH] = 0.0f; sh[1][NTH] = 0.0f; }

    float p1    = 0.0f;                       // E[i-1][j]  (own previous row)
    float Ldiag = (t == 0) ? 1.0f : 0.0f;     // E[i-1][j-1] (neighbor, two steps back); E[0][0]=1
    int   esum  = 0;                          // accumulated power-of-2 exponent

    // Prefill prefetch ring: slot k holds D for step s=k+1 -> row r = clamp(k - t)
    float ring[PRE];
#pragma unroll
    for (int k = 0; k < PRE; ++k) {
        int r = k - t;
        r = max(r, 0); r = min(r, NROW - 1);
        ring[k] = Db[r * NCOL];
    }
    __syncthreads();

    // 1024 steps (last step is a harmless no-op for all threads: i = 1024-t >= 513)
    // 64 chunks of 16; renormalize every 2 chunks (32 steps).
    int s = 1;
    for (int c = 0; c < 64; ++c) {
#pragma unroll
        for (int k = 0; k < PRE; ++k, ++s) {
            const int rb = k & 1;              // (s-1)&1, compile-time per k
            const int wb = rb ^ 1;             // s&1

            float L1   = sh[rb][t];            // E[i][j-1] (neighbor, previous step)
            float dval = ring[k];

            // refill slot for step s+PRE: row = s+PRE - t - 1, clamped
            {
                int r = s + PRE - t - 1;
                r = max(r, 0); r = min(r, NROW - 1);
                ring[k] = Db[r * NCOL];
            }

            // i = s - t. Pre-active threads (i <= 0) compute zeros (correct boundary
            // propagation); frozen threads (i > 512) must not touch state.
            if (s - t <= NROW) {
                float w = __expf(-dval);                 // off the dependency chain
                float v = w * ((L1 + p1) + Ldiag);
                sh[wb][t + 1] = v;
                p1 = v;
            }
            Ldiag = L1;                                  // neighbor's row becomes next diag
            __syncthreads();
        }

        if (c & 1) {
            // Renormalize the frontier by an exact power of two.
            // Last completed step s-1 is a multiple of 16 -> its write buffer is 0.
            float m = p1;                                 // all E >= 0
#pragma unroll
            for (int o = 16; o; o >>= 1)
                m = fmaxf(m, __shfl_xor_sync(0xffffffffu, m, o));
            if ((t & 31) == 0) red[t >> 5] = m;
            __syncthreads();
            float M = red[0];
#pragma unroll
            for (int q = 1; q < 16; ++q) M = fmaxf(M, red[q]);

            int e = ((__float_as_int(M) >> 23) & 0xFF) - 127;  // ilogb(M), M>0 normal
            if (e > 100) e = 100;
            if (e < -100) e = -100;
            if (e != 0) {
                float sc = __int_as_float((127 - e) << 23);    // exact 2^-e
                p1    *= sc;
                Ldiag *= sc;
                sh[0][t + 1] = p1;       // buffer 0 = the one read next step
                esum  += e;
            }
            __syncthreads();
        }
    }

    // Thread 511 holds E[512][512] (computed at step 1023, frozen at 1024).
    if (t == NTH - 1)
        out[b] = -((float)esum + __log2f(p1)) * LN2F;
}

extern "C" void kernel_launch(void* const* d_in, const int* in_sizes, int n_in,
                              void* d_out, int out_size) {
    const float* D = (const float*)d_in[0];
    float* out = (float*)d_out;
    int B = in_sizes[0] / (NROW * NCOL);   // 128
    softdtw_exp_kernel<<<B, NTH>>>(D, out);
}

// round 10
// speedup vs baseline: 1.0364x; 1.0059x over previous
#include <cuda_runtime.h>
#include <cuda_bf16.h>

// Soft-DTW forward, gamma=1, B=128, N=M=512.
// Exp-domain DP: E = exp(-R); E[i][j] = exp(-D[i-1][j-1]) * (E[i-1][j-1] + E[i-1][j] + E[i][j-1]).
// Anti-diagonal wavefront, one block per batch, one thread per column.
// Block-wide power-of-2 renormalization every 32 steps keeps E in fp32 range;
// integer exponent accumulator restores the log at the end.

#define NROW 512
#define NCOL 512
#define NTH  512
#define PRE  16                 // prefetch ring depth (registers)
#define LN2F 0.69314718055994530942f

__global__ __launch_bounds__(NTH, 1)
void softdtw_exp_kernel(const float* __restrict__ D, float* __restrict__ out) {
    __shared__ float sh[2][NTH + 1];   // halo buffers; sh[*][0] is the j=0 boundary (E=0)
    __shared__ float red[16];          // per-warp max for renormalization

    const int t = threadIdx.x;         // column j = t+1 (1-indexed)
    const int b = blockIdx.x;
    const float* Db = D + (size_t)b * NROW * NCOL + t;   // base of column t

    // init boundaries: E[0][j>=1] = 0, E[i][0] = 0, E[0][0] = 1
    sh[0][t] = 0.0f;
    sh[1][t] = 0.0f;
    if (t == 0) { sh[0][NTH] = 0.0f; sh[1][NTH] = 0.0f; }

    float p1    = 0.0f;                       // E[i-1][j]  (own previous row)
    float Ldiag = (t == 0) ? 1.0f : 0.0f;     // E[i-1][j-1] (neighbor, two steps back); E[0][0]=1
    int   esum  = 0;                          // accumulated power-of-2 exponent

    // Prefill prefetch ring: slot k holds D for step s=k+1 -> row r = clamp(k - t)
    float ring[PRE];
#pragma unroll
    for (int k = 0; k < PRE; ++k) {
        int r = k - t;
        r = max(r, 0); r = min(r, NROW - 1);
        ring[k] = Db[r * NCOL];
    }
    __syncthreads();

    // 1024 steps (last step is a harmless no-op for all threads: i = 1024-t >= 513)
    // 64 chunks of 16; renormalize every 2 chunks (32 steps).
    int s = 1;
    for (int c = 0; c < 64; ++c) {
#pragma unroll
        for (int k = 0; k < PRE; ++k, ++s) {
            const int rb = k & 1;              // (s-1)&1, compile-time per k
            const int wb = rb ^ 1;             // s&1

            float L1   = sh[rb][t];            // E[i][j-1] (neighbor, previous step)
            float dval = ring[k];

            // refill slot for step s+PRE: row = s+PRE - t - 1, clamped
            {
                int r = s + PRE - t - 1;
                r = max(r, 0); r = min(r, NROW - 1);
                ring[k] = Db[r * NCOL];
            }

            // i = s - t. Pre-active threads (i <= 0) compute zeros (correct boundary
            // propagation); frozen threads (i > 512) must not touch state.
            if (s - t <= NROW) {
                float w = __expf(-dval);                 // off the dependency chain
                float v = w * ((L1 + p1) + Ldiag);
                sh[wb][t + 1] = v;
                p1 = v;
            }
            Ldiag = L1;                                  // neighbor's row becomes next diag
            __syncthreads();
        }

        if (c & 1) {
            // Renormalize the frontier by an exact power of two.
            // Last completed step s-1 is a multiple of 16 -> its write buffer is 0.
            float m = p1;                                 // all E >= 0
#pragma unroll
            for (int o = 16; o; o >>= 1)
                m = fmaxf(m, __shfl_xor_sync(0xffffffffu, m, o));
            if ((t & 31) == 0) red[t >> 5] = m;
            __syncthreads();
            float M = red[0];
#pragma unroll
            for (int q = 1; q < 16; ++q) M = fmaxf(M, red[q]);

            int e = ((__float_as_int(M) >> 23) & 0xFF) - 127;  // ilogb(M), M>0 normal
            if (e > 100) e = 100;
            if (e < -100) e = -100;
            if (e != 0) {
                float sc = __int_as_float((127 - e) << 23);    // exact 2^-e
                p1    *= sc;
                Ldiag *= sc;
                sh[0][t + 1] = p1;       // buffer 0 = the one read next step
                esum  += e;
            }
            __syncthreads();
        }
    }

    // Thread 511 holds E[512][512] (computed at step 1023, frozen at 1024).
    if (t == NTH - 1)
        out[b] = -((float)esum + __log2f(p1)) * LN2F;
}

extern "C" void kernel_launch(void* const* d_in, const int* in_sizes, int n_in,
                              void* d_out, int out_size) {
    const float* D = (const float*)d_in[0];
    float* out = (float*)d_out;
    int B = in_sizes[0] / (NROW * NCOL);   // 128
    softdtw_exp_kernel<<<B, NTH>>>(D, out);
}

// round 11
// speedup vs baseline: 1.0376x; 1.0012x over previous
#include <cuda_runtime.h>
#include <cuda_bf16.h>

// Soft-DTW forward, gamma=1, B=128, N=M=512.
// Exp-domain DP: E = exp(-R); E[i][j] = exp(-D[i-1][j-1]) * (E[i-1][j-1] + E[i-1][j] + E[i][j-1]).
// Anti-diagonal wavefront, one block per batch, one thread per column.
// Block-wide power-of-2 renormalization every 32 steps keeps E in fp32 range;
// integer exponent accumulator restores the log at the end.

#define NROW 512
#define NCOL 512
#define NTH  512
#define PRE  16                 // prefetch ring depth (registers)
#define LN2F 0.69314718055994530942f

__global__ __launch_bounds__(NTH, 1)
void softdtw_exp_kernel(const float* __restrict__ D, float* __restrict__ out) {
    __shared__ float sh[2][NTH + 1];   // halo buffers; sh[*][0] is the j=0 boundary (E=0)
    __shared__ float red[16];          // per-warp max for renormalization

    const int t = threadIdx.x;         // column j = t+1 (1-indexed)
    const int b = blockIdx.x;
    const float* Db = D + (size_t)b * NROW * NCOL + t;   // base of column t

    // init boundaries: E[0][j>=1] = 0, E[i][0] = 0, E[0][0] = 1
    sh[0][t] = 0.0f;
    sh[1][t] = 0.0f;
    if (t == 0) { sh[0][NTH] = 0.0f; sh[1][NTH] = 0.0f; }

    float p1    = 0.0f;                       // E[i-1][j]  (own previous row)
    float Ldiag = (t == 0) ? 1.0f : 0.0f;     // E[i-1][j-1] (neighbor, two steps back); E[0][0]=1
    int   esum  = 0;                          // accumulated power-of-2 exponent

    // Prefill prefetch ring: slot k holds D for step s=k+1 -> row r = clamp(k - t)
    float ring[PRE];
#pragma unroll
    for (int k = 0; k < PRE; ++k) {
        int r = k - t;
        r = max(r, 0); r = min(r, NROW - 1);
        ring[k] = Db[r * NCOL];
    }
    __syncthreads();

    // 1024 steps (last step is a harmless no-op for all threads: i = 1024-t >= 513)
    // 64 chunks of 16; renormalize every 2 chunks (32 steps).
    int s = 1;
    for (int c = 0; c < 64; ++c) {
#pragma unroll
        for (int k = 0; k < PRE; ++k, ++s) {
            const int rb = k & 1;              // (s-1)&1, compile-time per k
            const int wb = rb ^ 1;             // s&1

            float L1   = sh[rb][t];            // E[i][j-1] (neighbor, previous step)
            float dval = ring[k];

            // refill slot for step s+PRE: row = s+PRE - t - 1, clamped
            {
                int r = s + PRE - t - 1;
                r = max(r, 0); r = min(r, NROW - 1);
                ring[k] = Db[r * NCOL];
            }

            // i = s - t. Pre-active threads (i <= 0) compute zeros (correct boundary
            // propagation); frozen threads (i > 512) must not touch state.
            if (s - t <= NROW) {
                float w = __expf(-dval);                 // off the dependency chain
                float v = w * ((L1 + p1) + Ldiag);
                sh[wb][t + 1] = v;
                p1 = v;
            }
            Ldiag = L1;                                  // neighbor's row becomes next diag
            __syncthreads();
        }

        if (c & 1) {
            // Renormalize the frontier by an exact power of two.
            // Last completed step s-1 is a multiple of 16 -> its write buffer is 0.
            float m = p1;                                 // all E >= 0
#pragma unroll
            for (int o = 16; o; o >>= 1)
                m = fmaxf(m, __shfl_xor_sync(0xffffffffu, m, o));
            if ((t & 31) == 0) red[t >> 5] = m;
            __syncthreads();
            float M = red[0];
#pragma unroll
            for (int q = 1; q < 16; ++q) M = fmaxf(M, red[q]);

            int e = ((__float_as_int(M) >> 23) & 0xFF) - 127;  // ilogb(M), M>0 normal
            if (e > 100) e = 100;
            if (e < -100) e = -100;
            if (e != 0) {
                float sc = __int_as_float((127 - e) << 23);    // exact 2^-e
                p1    *= sc;
                Ldiag *= sc;
                sh[0][t + 1] = p1;       // buffer 0 = the one read next step
                esum  += e;
            }
            __syncthreads();
        }
    }

    // Thread 511 holds E[512][512] (computed at step 1023, frozen at 1024).
    if (t == NTH - 1)
        out[b] = -((float)esum + __log2f(p1)) * LN2F;
}

extern "C" void kernel_launch(void* const* d_in, const int* in_sizes, int n_in,
                              void* d_out, int out_size) {
    const float* D = (const float*)d_in[0];
    float* out = (float*)d_out;
    int B = in_sizes[0] / (NROW * NCOL);   // 128
    softdtw_exp_kernel<<<B, NTH>>>(D, out);
}

// round 12
// speedup vs baseline: 1.0394x; 1.0018x over previous
#include <cuda_runtime.h>
#include <cuda_bf16.h>

// Soft-DTW forward, gamma=1, B=128, N=M=512.
// Exp-domain DP: E = exp(-R); E[i][j] = exp(-D[i-1][j-1]) * (E[i-1][j-1] + E[i-1][j] + E[i][j-1]).
// Anti-diagonal wavefront, one block per batch, one thread per column.
// Block-wide power-of-2 renormalization every 32 steps keeps E in fp32 range;
// integer exponent accumulator restores the log at the end.

#define NROW 512
#define NCOL 512
#define NTH  512
#define PRE  16                 // prefetch ring depth (registers)
#define LN2F 0.69314718055994530942f

__global__ __launch_bounds__(NTH, 1)
void softdtw_exp_kernel(const float* __restrict__ D, float* __restrict__ out) {
    __shared__ float sh[2][NTH + 1];   // halo buffers; sh[*][0] is the j=0 boundary (E=0)
    __shared__ float red[16];          // per-warp max for renormalization

    const int t = threadIdx.x;         // column j = t+1 (1-indexed)
    const int b = blockIdx.x;
    const float* Db = D + (size_t)b * NROW * NCOL + t;   // base of column t

    // init boundaries: E[0][j>=1] = 0, E[i][0] = 0, E[0][0] = 1
    sh[0][t] = 0.0f;
    sh[1][t] = 0.0f;
    if (t == 0) { sh[0][NTH] = 0.0f; sh[1][NTH] = 0.0f; }

    float p1    = 0.0f;                       // E[i-1][j]  (own previous row)
    float Ldiag = (t == 0) ? 1.0f : 0.0f;     // E[i-1][j-1] (neighbor, two steps back); E[0][0]=1
    int   esum  = 0;                          // accumulated power-of-2 exponent

    // Prefill prefetch ring: slot k holds D for step s=k+1 -> row r = clamp(k - t)
    float ring[PRE];
#pragma unroll
    for (int k = 0; k < PRE; ++k) {
        int r = k - t;
        r = max(r, 0); r = min(r, NROW - 1);
        ring[k] = Db[r * NCOL];
    }
    __syncthreads();

    // 1024 steps (last step is a harmless no-op for all threads: i = 1024-t >= 513)
    // 64 chunks of 16; renormalize every 2 chunks (32 steps).
    int s = 1;
    for (int c = 0; c < 64; ++c) {
#pragma unroll
        for (int k = 0; k < PRE; ++k, ++s) {
            const int rb = k & 1;              // (s-1)&1, compile-time per k
            const int wb = rb ^ 1;             // s&1

            float L1   = sh[rb][t];            // E[i][j-1] (neighbor, previous step)
            float dval = ring[k];

            // refill slot for step s+PRE: row = s+PRE - t - 1, clamped
            {
                int r = s + PRE - t - 1;
                r = max(r, 0); r = min(r, NROW - 1);
                ring[k] = Db[r * NCOL];
            }

            // i = s - t. Pre-active threads (i <= 0) compute zeros (correct boundary
            // propagation); frozen threads (i > 512) must not touch state.
            if (s - t <= NROW) {
                float w = __expf(-dval);                 // off the dependency chain
                float v = w * ((L1 + p1) + Ldiag);
                sh[wb][t + 1] = v;
                p1 = v;
            }
            Ldiag = L1;                                  // neighbor's row becomes next diag
            __syncthreads();
        }

        if (c & 1) {
            // Renormalize the frontier by an exact power of two.
            // Last completed step s-1 is a multiple of 16 -> its write buffer is 0.
            float m = p1;                                 // all E >= 0
#pragma unroll
            for (int o = 16; o; o >>= 1)
                m = fmaxf(m, __shfl_xor_sync(0xffffffffu, m, o));
            if ((t & 31) == 0) red[t >> 5] = m;
            __syncthreads();
            float M = red[0];
#pragma unroll
            for (int q = 1; q < 16; ++q) M = fmaxf(M, red[q]);

            int e = ((__float_as_int(M) >> 23) & 0xFF) - 127;  // ilogb(M), M>0 normal
            if (e > 100) e = 100;
            if (e < -100) e = -100;
            if (e != 0) {
                float sc = __int_as_float((127 - e) << 23);    // exact 2^-e
                p1    *= sc;
                Ldiag *= sc;
                sh[0][t + 1] = p1;       // buffer 0 = the one read next step
                esum  += e;
            }
            __syncthreads();
        }
    }

    // Thread 511 holds E[512][512] (computed at step 1023, frozen at 1024).
    if (t == NTH - 1)
        out[b] = -((float)esum + __log2f(p1)) * LN2F;
}

extern "C" void kernel_launch(void* const* d_in, const int* in_sizes, int n_in,
                              void* d_out, int out_size) {
    const float* D = (const float*)d_in[0];
    float* out = (float*)d_out;
    int B = in_sizes[0] / (NROW * NCOL);   // 128
    softdtw_exp_kernel<<<B, NTH>>>(D, out);
}